// round 1
// baseline (speedup 1.0000x reference)
#include <cuda_runtime.h>

// Problem constants
#define BSZ     256
#define IDIM    182
#define TSTEPS  2000
#define OCH     2
#define THREADS 512
#define CHUNK   32
#define NCHUNK  64          // 64*32 = 2048 >= 2000
#define TPAD    2112        // 2048 + 64 skew slots

__device__ __forceinline__ int skew(int t) { return t + (t >> 5); }

__global__ __launch_bounds__(THREADS, 2)
void snn_decoder_kernel(const float* __restrict__ inp,   // [B, I, T]
                        const float* __restrict__ W,     // [O, I]
                        const float* __restrict__ bias,  // [O]
                        const float* __restrict__ alpha, // [O]
                        const float* __restrict__ beta,  // [O]
                        float* __restrict__ out)         // [B, T, O]
{
    __shared__ float Wsh[OCH][IDIM];
    __shared__ float curr[OCH][TPAD];
    __shared__ float vsyn[OCH][NCHUNK], vmem[OCH][NCHUNK];
    __shared__ float Psyn[OCH][NCHUNK], Pmem[OCH][NCHUNK];

    const int tid = threadIdx.x;
    const int b   = blockIdx.x;

    // ---- load W into smem ----
    for (int k = tid; k < OCH * IDIM; k += THREADS)
        Wsh[k / IDIM][k % IDIM] = W[k];
    __syncthreads();

    // ---- phase 1: compute curr[o][t] = dot(inputs[b,:,t], W[o,:]) + bias[o] ----
    const float* ib = inp + (size_t)b * IDIM * TSTEPS;

    if (tid < TSTEPS / 4) {
        const int t0 = tid * 4;
        float4 acc0 = make_float4(0.f, 0.f, 0.f, 0.f);
        float4 acc1 = make_float4(0.f, 0.f, 0.f, 0.f);
        #pragma unroll 2
        for (int i = 0; i < IDIM; i++) {
            float4 x = *reinterpret_cast<const float4*>(ib + (size_t)i * TSTEPS + t0);
            const float w0 = Wsh[0][i];
            const float w1 = Wsh[1][i];
            acc0.x = fmaf(w0, x.x, acc0.x); acc0.y = fmaf(w0, x.y, acc0.y);
            acc0.z = fmaf(w0, x.z, acc0.z); acc0.w = fmaf(w0, x.w, acc0.w);
            acc1.x = fmaf(w1, x.x, acc1.x); acc1.y = fmaf(w1, x.y, acc1.y);
            acc1.z = fmaf(w1, x.z, acc1.z); acc1.w = fmaf(w1, x.w, acc1.w);
        }
        const float b0 = __ldg(&bias[0]);
        const float b1 = __ldg(&bias[1]);
        curr[0][skew(t0 + 0)] = acc0.x + b0;
        curr[0][skew(t0 + 1)] = acc0.y + b0;
        curr[0][skew(t0 + 2)] = acc0.z + b0;
        curr[0][skew(t0 + 3)] = acc0.w + b0;
        curr[1][skew(t0 + 0)] = acc1.x + b1;
        curr[1][skew(t0 + 1)] = acc1.y + b1;
        curr[1][skew(t0 + 2)] = acc1.z + b1;
        curr[1][skew(t0 + 3)] = acc1.w + b1;
    } else if (tid < 512) {
        // zero-pad t in [2000, 2048)
        const int t0 = tid * 4;
        if (t0 < NCHUNK * CHUNK) {
            #pragma unroll
            for (int k = 0; k < 4; k++) {
                curr[0][skew(t0 + k)] = 0.f;
                curr[1][skew(t0 + k)] = 0.f;
            }
        }
    }
    __syncthreads();

    // ---- phase 2a: per-chunk scan with zero initial state ----
    if (tid < OCH * NCHUNK) {
        const int o = tid >> 6;
        const int j = tid & 63;
        const float a  = __saturatef(__ldg(&alpha[o]));  // clamp to [0,1]
        const float bt = __saturatef(__ldg(&beta[o]));
        float syn = 0.f, mem = 0.f;
        const int tb = j * CHUNK;
        #pragma unroll
        for (int k = 0; k < CHUNK; k++) {
            const float c = curr[o][skew(tb + k)];
            syn = fmaf(a, syn, c);
            mem = fmaf(bt, mem, syn);
        }
        vsyn[o][j] = syn;
        vmem[o][j] = mem;
    }
    __syncthreads();

    // ---- phase 2b: serial composition of the 64 chunk maps (2 threads) ----
    if (tid < OCH) {
        const int o = tid;
        const float a  = __saturatef(__ldg(&alpha[o]));
        const float bt = __saturatef(__ldg(&beta[o]));
        // Columns of M^CHUNK:  syn_L = A*syn0 ; mem_L = C*syn0 + Bc*mem0  (zero input)
        float A = 1.f, Bc = 1.f, C = 0.f;
        #pragma unroll
        for (int k = 0; k < CHUNK; k++) {
            A  = a * A;
            C  = fmaf(bt, C, A);
            Bc = bt * Bc;
        }
        float Ss = 0.f, Sm = 0.f;
        for (int k = 0; k < NCHUNK; k++) {
            Psyn[o][k] = Ss;
            Pmem[o][k] = Sm;
            const float ns = fmaf(A, Ss, vsyn[o][k]);
            const float nm = fmaf(C, Ss, fmaf(Bc, Sm, vmem[o][k]));
            Ss = ns;
            Sm = nm;
        }
    }
    __syncthreads();

    // ---- phase 2c: replay each chunk with its true prefix state, write output ----
    if (tid < OCH * NCHUNK) {
        const int o = tid >> 6;
        const int j = tid & 63;
        const float a  = __saturatef(__ldg(&alpha[o]));
        const float bt = __saturatef(__ldg(&beta[o]));
        float syn = Psyn[o][j];
        float mem = Pmem[o][j];
        const int tb = j * CHUNK;
        float* ob = out + (size_t)b * TSTEPS * OCH;
        #pragma unroll
        for (int k = 0; k < CHUNK; k++) {
            const int t = tb + k;
            const float c = curr[o][skew(t)];
            syn = fmaf(a, syn, c);
            mem = fmaf(bt, mem, syn);
            if (t < TSTEPS)
                ob[t * OCH + o] = mem;
        }
    }
}

extern "C" void kernel_launch(void* const* d_in, const int* in_sizes, int n_in,
                              void* d_out, int out_size)
{
    const float* inp   = (const float*)d_in[0]; // [256,182,2000]
    const float* W     = (const float*)d_in[1]; // [2,182]
    const float* bias  = (const float*)d_in[2]; // [2]
    const float* alpha = (const float*)d_in[3]; // [2]
    const float* beta  = (const float*)d_in[4]; // [2]
    float* out = (float*)d_out;                 // [256,2000,2]

    snn_decoder_kernel<<<BSZ, THREADS>>>(inp, W, bias, alpha, beta, out);
}

// round 2
// speedup vs baseline: 1.0004x; 1.0004x over previous
#include <cuda_runtime.h>

// Problem constants
#define BSZ     256
#define IDIM    182
#define TSTEPS  2000
#define OCH     2
#define CHUNK   32
#define NCHUNK  64          // 64*32 = 2048 >= 2000
#define TPAD    2112        // 2048 + 64 skew slots

// 4 MB scratch for per-step currents, layout [b][o][t]
__device__ float g_curr[(size_t)BSZ * OCH * TSTEPS];

__device__ __forceinline__ int skew(int t) { return t + (t >> 5); }

// ---------------------------------------------------------------------------
// K1: pure streaming GEMM.  curr[b][o][t] = dot(inputs[b,:,t], W[o,:]) + bias[o]
// grid = 500 blocks x 256 threads; each thread owns one (b, t0..t0+3) column.
// 500*256 = 128000 = 256 b * 500 float4-columns.  Fully coalesced float4 reads.
// ---------------------------------------------------------------------------
__global__ __launch_bounds__(256)
void snn_gemm_kernel(const float* __restrict__ inp,   // [B, I, T]
                     const float* __restrict__ W,     // [O, I]
                     const float* __restrict__ bias)  // [O]
{
    __shared__ float Wsh[OCH][IDIM];
    __shared__ float Bsh[OCH];

    const int tid = threadIdx.x;
    for (int k = tid; k < OCH * IDIM; k += 256)
        Wsh[k / IDIM][k % IDIM] = W[k];
    if (tid < OCH)
        Bsh[tid] = bias[tid];
    __syncthreads();

    const int g  = blockIdx.x * 256 + tid;  // 0..127999
    const int b  = g / 500;
    const int c  = g % 500;
    const int t0 = c * 4;

    const float* ib = inp + (size_t)b * IDIM * TSTEPS + t0;

    float4 acc0 = make_float4(0.f, 0.f, 0.f, 0.f);
    float4 acc1 = make_float4(0.f, 0.f, 0.f, 0.f);

    #pragma unroll 7
    for (int i = 0; i < IDIM; i++) {
        const float4 x = *reinterpret_cast<const float4*>(ib + (size_t)i * TSTEPS);
        const float w0 = Wsh[0][i];
        const float w1 = Wsh[1][i];
        acc0.x = fmaf(w0, x.x, acc0.x); acc0.y = fmaf(w0, x.y, acc0.y);
        acc0.z = fmaf(w0, x.z, acc0.z); acc0.w = fmaf(w0, x.w, acc0.w);
        acc1.x = fmaf(w1, x.x, acc1.x); acc1.y = fmaf(w1, x.y, acc1.y);
        acc1.z = fmaf(w1, x.z, acc1.z); acc1.w = fmaf(w1, x.w, acc1.w);
    }

    const float b0 = Bsh[0];
    const float b1 = Bsh[1];
    acc0.x += b0; acc0.y += b0; acc0.z += b0; acc0.w += b0;
    acc1.x += b1; acc1.y += b1; acc1.z += b1; acc1.w += b1;

    float* dst0 = g_curr + ((size_t)b * OCH + 0) * TSTEPS + t0;
    float* dst1 = g_curr + ((size_t)b * OCH + 1) * TSTEPS + t0;
    *reinterpret_cast<float4*>(dst0) = acc0;
    *reinterpret_cast<float4*>(dst1) = acc1;
}

// ---------------------------------------------------------------------------
// K2: chunked parallel scan of the 2-state linear recurrence, one block per b.
//   syn_t = a*syn_{t-1} + curr_t ;  mem_t = m*mem_{t-1} + syn_t
// 64 threads; thread j owns chunk of 32 steps, handles BOTH output channels.
// ---------------------------------------------------------------------------
__global__ __launch_bounds__(64)
void snn_scan_kernel(const float* __restrict__ alpha,
                     const float* __restrict__ beta,
                     float* __restrict__ out)          // [B, T, O]
{
    __shared__ float curr[OCH][TPAD];
    __shared__ float vsyn[OCH][NCHUNK], vmem[OCH][NCHUNK];
    __shared__ float Psyn[OCH][NCHUNK], Pmem[OCH][NCHUNK];

    const int j  = threadIdx.x;   // chunk index 0..63
    const int b  = blockIdx.x;
    const int tb = j * CHUNK;

    const float a0 = __saturatef(alpha[0]);
    const float a1 = __saturatef(alpha[1]);
    const float m0 = __saturatef(beta[0]);
    const float m1 = __saturatef(beta[1]);

    // ---- phase A: load chunk currents, stage in smem, local scan from zero ----
    #pragma unroll
    for (int o = 0; o < OCH; o++) {
        const float a = o ? a1 : a0;
        const float m = o ? m1 : m0;
        const float* src = g_curr + ((size_t)b * OCH + o) * TSTEPS;
        float syn = 0.f, mem = 0.f;
        #pragma unroll
        for (int q = 0; q < CHUNK / 4; q++) {
            const int t = tb + q * 4;
            float4 x = (t < TSTEPS)
                     ? *reinterpret_cast<const float4*>(src + t)
                     : make_float4(0.f, 0.f, 0.f, 0.f);
            curr[o][skew(t + 0)] = x.x;
            curr[o][skew(t + 1)] = x.y;
            curr[o][skew(t + 2)] = x.z;
            curr[o][skew(t + 3)] = x.w;
            syn = fmaf(a, syn, x.x); mem = fmaf(m, mem, syn);
            syn = fmaf(a, syn, x.y); mem = fmaf(m, mem, syn);
            syn = fmaf(a, syn, x.z); mem = fmaf(m, mem, syn);
            syn = fmaf(a, syn, x.w); mem = fmaf(m, mem, syn);
        }
        vsyn[o][j] = syn;
        vmem[o][j] = mem;
    }
    __syncthreads();

    // ---- phase B: serial composition of the 64 chunk maps (threads 0,1) ----
    if (j < OCH) {
        const int o   = j;
        const float a = o ? a1 : a0;
        const float m = o ? m1 : m0;
        // Columns of M^CHUNK (per-step M = [[a,0],[a,m]]):
        //   syn_L = A*syn0 ;  mem_L = C*syn0 + Bc*mem0   (zero input)
        float A = 1.f, Bc = 1.f, C = 0.f;
        #pragma unroll
        for (int k = 0; k < CHUNK; k++) {
            A  = a * A;
            C  = fmaf(m, C, A);
            Bc = m * Bc;
        }
        float Ss = 0.f, Sm = 0.f;
        for (int k = 0; k < NCHUNK; k++) {
            Psyn[o][k] = Ss;
            Pmem[o][k] = Sm;
            const float ns = fmaf(A, Ss, vsyn[o][k]);
            const float nm = fmaf(C, Ss, fmaf(Bc, Sm, vmem[o][k]));
            Ss = ns;
            Sm = nm;
        }
    }
    __syncthreads();

    // ---- phase C: replay with true prefix state, write interleaved float2 ----
    float s0 = Psyn[0][j], q0 = Pmem[0][j];
    float s1 = Psyn[1][j], q1 = Pmem[1][j];
    float2* ob = reinterpret_cast<float2*>(out) + (size_t)b * TSTEPS;

    #pragma unroll
    for (int k = 0; k < CHUNK; k++) {
        const int t = tb + k;
        const float c0 = curr[0][skew(t)];
        const float c1 = curr[1][skew(t)];
        s0 = fmaf(a0, s0, c0); q0 = fmaf(m0, q0, s0);
        s1 = fmaf(a1, s1, c1); q1 = fmaf(m1, q1, s1);
        if (t < TSTEPS)
            ob[t] = make_float2(q0, q1);
    }
}

extern "C" void kernel_launch(void* const* d_in, const int* in_sizes, int n_in,
                              void* d_out, int out_size)
{
    const float* inp   = (const float*)d_in[0]; // [256,182,2000]
    const float* W     = (const float*)d_in[1]; // [2,182]
    const float* bias  = (const float*)d_in[2]; // [2]
    const float* alpha = (const float*)d_in[3]; // [2]
    const float* beta  = (const float*)d_in[4]; // [2]
    float* out = (float*)d_out;                 // [256,2000,2]

    snn_gemm_kernel<<<500, 256>>>(inp, W, bias);
    snn_scan_kernel<<<BSZ, 64>>>(alpha, beta, out);
}

// round 3
// speedup vs baseline: 1.0577x; 1.0572x over previous
#include <cuda_runtime.h>

// Problem constants
#define BSZ     256
#define IDIM    182
#define TSTEPS  2000
#define OCH     2
#define CHUNK   8            // steps per thread in scan kernel
#define NCHUNK  256          // 256*8 = 2048 >= 2000

// 4 MB scratch for per-step currents, layout [b][o][t]
__device__ float g_curr[(size_t)BSZ * OCH * TSTEPS];

// ---------------------------------------------------------------------------
// K1: pure streaming GEMM.  curr[b][o][t] = dot(inputs[b,:,t], W[o,:]) + bias[o]
// grid = 500 blocks x 256 threads; each thread owns one (b, t0..t0+3) column.
// Input read with __ldcs (evict-first) so the 4MB scratch stays L2-resident.
// ---------------------------------------------------------------------------
__global__ __launch_bounds__(256)
void snn_gemm_kernel(const float* __restrict__ inp,   // [B, I, T]
                     const float* __restrict__ W,     // [O, I]
                     const float* __restrict__ bias)  // [O]
{
    __shared__ float Wsh[OCH][IDIM];
    __shared__ float Bsh[OCH];

    const int tid = threadIdx.x;
    for (int k = tid; k < OCH * IDIM; k += 256)
        Wsh[k / IDIM][k % IDIM] = W[k];
    if (tid < OCH)
        Bsh[tid] = bias[tid];
    __syncthreads();

    const int g  = blockIdx.x * 256 + tid;  // 0..127999
    const int b  = g / 500;
    const int c  = g % 500;
    const int t0 = c * 4;

    const float* ib = inp + (size_t)b * IDIM * TSTEPS + t0;

    float4 acc0 = make_float4(0.f, 0.f, 0.f, 0.f);
    float4 acc1 = make_float4(0.f, 0.f, 0.f, 0.f);

    #pragma unroll 7
    for (int i = 0; i < IDIM; i++) {
        const float4 x = __ldcs(reinterpret_cast<const float4*>(ib + (size_t)i * TSTEPS));
        const float w0 = Wsh[0][i];
        const float w1 = Wsh[1][i];
        acc0.x = fmaf(w0, x.x, acc0.x); acc0.y = fmaf(w0, x.y, acc0.y);
        acc0.z = fmaf(w0, x.z, acc0.z); acc0.w = fmaf(w0, x.w, acc0.w);
        acc1.x = fmaf(w1, x.x, acc1.x); acc1.y = fmaf(w1, x.y, acc1.y);
        acc1.z = fmaf(w1, x.z, acc1.z); acc1.w = fmaf(w1, x.w, acc1.w);
    }

    const float b0 = Bsh[0];
    const float b1 = Bsh[1];
    acc0.x += b0; acc0.y += b0; acc0.z += b0; acc0.w += b0;
    acc1.x += b1; acc1.y += b1; acc1.z += b1; acc1.w += b1;

    float* dst0 = g_curr + ((size_t)b * OCH + 0) * TSTEPS + t0;
    float* dst1 = g_curr + ((size_t)b * OCH + 1) * TSTEPS + t0;
    *reinterpret_cast<float4*>(dst0) = acc0;
    *reinterpret_cast<float4*>(dst1) = acc1;
}

// ---------------------------------------------------------------------------
// K2: log-depth chunked scan of the 2-state linear recurrence.
//   syn_t = a*syn_{t-1} + c_t ;  mem_t = m*mem_{t-1} + syn_t
// One block per b, 256 threads, CHUNK=8 steps/thread, both channels per thread.
// Chunk transition matrix P = M^8 is identical for all chunks, so a
// Kogge-Stone scan with combine v_j <- P^d * v_{j-d} + v_j applies, with P^d
// produced by repeated squaring between steps. Cross-warp fixup via 8 warp
// totals (serial, 8 iters) and per-lane P^lane built by bit-select.
// ---------------------------------------------------------------------------
__global__ __launch_bounds__(256)
void snn_scan_kernel(const float* __restrict__ alpha,
                     const float* __restrict__ beta,
                     float* __restrict__ out)          // [B, T, O]
{
    __shared__ float Ts[OCH][8][2];   // warp totals (syn, mem)
    __shared__ float Es[OCH][8][2];   // warp exclusive prefixes

    const int j    = threadIdx.x;     // chunk index 0..255
    const int lane = j & 31;
    const int w    = j >> 5;
    const int b    = blockIdx.x;
    const int t0   = j * CHUNK;
    const bool live = (t0 < TSTEPS);  // 2000 = 8*250: chunks 0..249 fully live

    float a[OCH], m[OCH];
    a[0] = __saturatef(alpha[0]); a[1] = __saturatef(alpha[1]);
    m[0] = __saturatef(beta[0]);  m[1] = __saturatef(beta[1]);

    // ---- phase A: load chunk currents, local scan from zero state ----
    float c[OCH][CHUNK];
    float vs[OCH], vm[OCH];
    #pragma unroll
    for (int o = 0; o < OCH; o++) {
        const float* src = g_curr + ((size_t)b * OCH + o) * TSTEPS + t0;
        float4 x0 = make_float4(0.f, 0.f, 0.f, 0.f);
        float4 x1 = make_float4(0.f, 0.f, 0.f, 0.f);
        if (live) {
            x0 = *reinterpret_cast<const float4*>(src);
            x1 = *reinterpret_cast<const float4*>(src + 4);
        }
        c[o][0] = x0.x; c[o][1] = x0.y; c[o][2] = x0.z; c[o][3] = x0.w;
        c[o][4] = x1.x; c[o][5] = x1.y; c[o][6] = x1.z; c[o][7] = x1.w;
        float s = 0.f, q = 0.f;
        #pragma unroll
        for (int k = 0; k < CHUNK; k++) {
            s = fmaf(a[o], s, c[o][k]);
            q = fmaf(m[o], q, s);
        }
        vs[o] = s; vm[o] = q;
    }

    // ---- P = M^CHUNK per channel:  M = [[a,0],[a,m]], M^k = [[A,0],[C,B]] ----
    float PA[OCH], PB[OCH], PC[OCH];
    #pragma unroll
    for (int o = 0; o < OCH; o++) {
        float A = 1.f, B = 1.f, C = 0.f;
        #pragma unroll
        for (int k = 0; k < CHUNK; k++) {
            A = a[o] * A;
            C = fmaf(m[o], C, A);
            B = m[o] * B;
        }
        PA[o] = A; PB[o] = B; PC[o] = C;
    }

    // ---- phase B: Kogge-Stone intra-warp scan; build L = P^lane on the fly ----
    float LA[OCH] = {1.f, 1.f}, LB[OCH] = {1.f, 1.f}, LC[OCH] = {0.f, 0.f};

    #pragma unroll
    for (int d = 1; d <= 16; d <<= 1) {
        // accumulate lane power (P currently holds P^d)
        #pragma unroll
        for (int o = 0; o < OCH; o++) {
            if (lane & d) {
                const float nA = LA[o] * PA[o];
                const float nB = LB[o] * PB[o];
                const float nC = fmaf(LC[o], PA[o], LB[o] * PC[o]);
                LA[o] = nA; LB[o] = nB; LC[o] = nC;
            }
        }
        // combine with lane-d earlier element
        #pragma unroll
        for (int o = 0; o < OCH; o++) {
            const float ws = __shfl_up_sync(0xffffffffu, vs[o], d);
            const float wq = __shfl_up_sync(0xffffffffu, vm[o], d);
            if (lane >= d) {
                vm[o] = fmaf(PC[o], ws, fmaf(PB[o], wq, vm[o]));
                vs[o] = fmaf(PA[o], ws, vs[o]);
            }
        }
        // square P for next offset
        #pragma unroll
        for (int o = 0; o < OCH; o++) {
            PC[o] = PC[o] * (PA[o] + PB[o]);
            PA[o] = PA[o] * PA[o];
            PB[o] = PB[o] * PB[o];
        }
    }
    // P now holds P^32 (warp-span matrix)

    // warp totals -> smem
    if (lane == 31) {
        #pragma unroll
        for (int o = 0; o < OCH; o++) {
            Ts[o][w][0] = vs[o];
            Ts[o][w][1] = vm[o];
        }
    }
    __syncthreads();

    // serial exclusive prefix over 8 warp totals (threads 0 and 1, one channel each)
    if (j < OCH) {
        const int o = j;
        float Ss = 0.f, Sm = 0.f;
        #pragma unroll
        for (int k = 0; k < 8; k++) {
            Es[o][k][0] = Ss;
            Es[o][k][1] = Sm;
            const float ts = Ts[o][k][0];
            const float tm = Ts[o][k][1];
            const float ns = fmaf(PA[o], Ss, ts);
            const float nm = fmaf(PC[o], Ss, fmaf(PB[o], Sm, tm));
            Ss = ns; Sm = nm;
        }
    }
    __syncthreads();

    // ---- phase C: chunk prefix state = P^lane * E_w + intra-warp exclusive ----
    if (live) {
        float2* ob = reinterpret_cast<float2*>(out) + (size_t)b * TSTEPS + t0;
        float pre_s[OCH], pre_m[OCH];
        #pragma unroll
        for (int o = 0; o < OCH; o++) {
            float Xs = __shfl_up_sync(0xffffffffu, vs[o], 1);
            float Xm = __shfl_up_sync(0xffffffffu, vm[o], 1);
            if (lane == 0) { Xs = 0.f; Xm = 0.f; }
            const float es = Es[o][w][0];
            const float em = Es[o][w][1];
            pre_s[o] = fmaf(LA[o], es, Xs);
            pre_m[o] = fmaf(LC[o], es, fmaf(LB[o], em, Xm));
        }
        float s0 = pre_s[0], q0 = pre_m[0];
        float s1 = pre_s[1], q1 = pre_m[1];
        #pragma unroll
        for (int k = 0; k < CHUNK; k++) {
            s0 = fmaf(a[0], s0, c[0][k]); q0 = fmaf(m[0], q0, s0);
            s1 = fmaf(a[1], s1, c[1][k]); q1 = fmaf(m[1], q1, s1);
            ob[k] = make_float2(q0, q1);
        }
    }
}

extern "C" void kernel_launch(void* const* d_in, const int* in_sizes, int n_in,
                              void* d_out, int out_size)
{
    const float* inp   = (const float*)d_in[0]; // [256,182,2000]
    const float* W     = (const float*)d_in[1]; // [2,182]
    const float* bias  = (const float*)d_in[2]; // [2]
    const float* alpha = (const float*)d_in[3]; // [2]
    const float* beta  = (const float*)d_in[4]; // [2]
    float* out = (float*)d_out;                 // [256,2000,2]

    snn_gemm_kernel<<<500, 256>>>(inp, W, bias);
    snn_scan_kernel<<<BSZ, 256>>>(alpha, beta, out);
}

// round 4
// speedup vs baseline: 1.1208x; 1.0597x over previous
#include <cuda_runtime.h>

// Problem constants
#define BSZ     256
#define IDIM    182
#define TSTEPS  2000
#define OCH     2
#define CHUNK   8            // steps per thread in scan phase
#define GRID    500          // 500*256 threads = 128000 = 256 b * 500 float4-cols

// 4 MB scratch for per-step currents, layout [b][o][t]
__device__ float g_curr[(size_t)BSZ * OCH * TSTEPS];

// software grid barrier (generation counter; replay-safe)
__device__ unsigned g_bar_count = 0;
__device__ volatile unsigned g_bar_phase = 0;

// ---------------------------------------------------------------------------
// Fused persistent kernel:
//  phase 1 (all 500 CTAs): streaming GEMM  curr[b][o][t] = <inp[b,:,t], W[o,:]> + bias
//  grid barrier
//  phase 2 (CTAs 0..255): log-depth chunked scan of the 2-state recurrence
//    syn_t = a*syn_{t-1} + c_t ;  mem_t = m*mem_{t-1} + syn_t
// __launch_bounds__(256,4) caps regs at 64 -> >=4 CTAs/SM -> 592 resident >= 500
// (all CTAs co-resident in one wave; the spin barrier cannot deadlock).
// ---------------------------------------------------------------------------
__global__ __launch_bounds__(256, 4)
void snn_fused_kernel(const float* __restrict__ inp,   // [B, I, T]
                      const float* __restrict__ W,     // [O, I]
                      const float* __restrict__ bias,  // [O]
                      const float* __restrict__ alpha,
                      const float* __restrict__ beta,
                      float* __restrict__ out)         // [B, T, O]
{
    __shared__ float Wsh[OCH][IDIM];
    __shared__ float Bsh[OCH];
    __shared__ float Ts[OCH][8][2];   // warp totals (syn, mem)
    __shared__ float Es[OCH][8][2];   // warp exclusive prefixes

    const int tid = threadIdx.x;

    // ======================= phase 1: GEMM =======================
    for (int k = tid; k < OCH * IDIM; k += 256)
        Wsh[k / IDIM][k % IDIM] = W[k];
    if (tid < OCH)
        Bsh[tid] = bias[tid];
    __syncthreads();

    {
        const int g  = blockIdx.x * 256 + tid;  // 0..127999
        const int bb = g / 500;
        const int c  = g % 500;
        const int t0 = c * 4;

        const float* ib = inp + (size_t)bb * IDIM * TSTEPS + t0;

        float4 acc0 = make_float4(0.f, 0.f, 0.f, 0.f);
        float4 acc1 = make_float4(0.f, 0.f, 0.f, 0.f);

        #pragma unroll 7
        for (int i = 0; i < IDIM; i++) {
            const float4 x = __ldcs(reinterpret_cast<const float4*>(ib + (size_t)i * TSTEPS));
            const float w0 = Wsh[0][i];
            const float w1 = Wsh[1][i];
            acc0.x = fmaf(w0, x.x, acc0.x); acc0.y = fmaf(w0, x.y, acc0.y);
            acc0.z = fmaf(w0, x.z, acc0.z); acc0.w = fmaf(w0, x.w, acc0.w);
            acc1.x = fmaf(w1, x.x, acc1.x); acc1.y = fmaf(w1, x.y, acc1.y);
            acc1.z = fmaf(w1, x.z, acc1.z); acc1.w = fmaf(w1, x.w, acc1.w);
        }

        const float b0 = Bsh[0];
        const float b1 = Bsh[1];
        acc0.x += b0; acc0.y += b0; acc0.z += b0; acc0.w += b0;
        acc1.x += b1; acc1.y += b1; acc1.z += b1; acc1.w += b1;

        float* dst0 = g_curr + ((size_t)bb * OCH + 0) * TSTEPS + t0;
        float* dst1 = g_curr + ((size_t)bb * OCH + 1) * TSTEPS + t0;
        *reinterpret_cast<float4*>(dst0) = acc0;
        *reinterpret_cast<float4*>(dst1) = acc1;
    }

    // ======================= grid barrier =======================
    const unsigned gen = g_bar_phase;   // volatile read, before arrival
    __syncthreads();                    // all threads of this block hold gen
    __threadfence();                    // g_curr writes visible device-wide
    if (tid == 0) {
        const unsigned prev = atomicAdd(&g_bar_count, 1);
        if (prev == GRID - 1) {
            g_bar_count = 0;            // reset for next graph replay
            __threadfence();
            g_bar_phase = gen + 1;      // release
        }
    }
    if (blockIdx.x >= BSZ) return;      // non-scan blocks leave after arriving

    if (tid == 0) {
        while (g_bar_phase == gen) { /* spin */ }
    }
    __syncthreads();
    __threadfence();                    // acquire: see all g_curr writes

    // ======================= phase 2: scan =======================
    const int j    = tid;               // chunk index 0..255
    const int lane = j & 31;
    const int w    = j >> 5;
    const int b    = blockIdx.x;
    const int t0   = j * CHUNK;
    const bool live = (t0 < TSTEPS);    // 2000 = 8*250

    float a[OCH], m[OCH];
    a[0] = __saturatef(alpha[0]); a[1] = __saturatef(alpha[1]);
    m[0] = __saturatef(beta[0]);  m[1] = __saturatef(beta[1]);

    // phase A: load chunk currents, local scan from zero state
    float c[OCH][CHUNK];
    float vs[OCH], vm[OCH];
    #pragma unroll
    for (int o = 0; o < OCH; o++) {
        const float* src = g_curr + ((size_t)b * OCH + o) * TSTEPS + t0;
        float4 x0 = make_float4(0.f, 0.f, 0.f, 0.f);
        float4 x1 = make_float4(0.f, 0.f, 0.f, 0.f);
        if (live) {
            x0 = *reinterpret_cast<const float4*>(src);
            x1 = *reinterpret_cast<const float4*>(src + 4);
        }
        c[o][0] = x0.x; c[o][1] = x0.y; c[o][2] = x0.z; c[o][3] = x0.w;
        c[o][4] = x1.x; c[o][5] = x1.y; c[o][6] = x1.z; c[o][7] = x1.w;
        float s = 0.f, q = 0.f;
        #pragma unroll
        for (int k = 0; k < CHUNK; k++) {
            s = fmaf(a[o], s, c[o][k]);
            q = fmaf(m[o], q, s);
        }
        vs[o] = s; vm[o] = q;
    }

    // P = M^CHUNK per channel:  M = [[a,0],[a,m]], M^k = [[A,0],[C,B]]
    float PA[OCH], PB[OCH], PC[OCH];
    #pragma unroll
    for (int o = 0; o < OCH; o++) {
        float A = 1.f, B = 1.f, C = 0.f;
        #pragma unroll
        for (int k = 0; k < CHUNK; k++) {
            A = a[o] * A;
            C = fmaf(m[o], C, A);
            B = m[o] * B;
        }
        PA[o] = A; PB[o] = B; PC[o] = C;
    }

    // phase B: Kogge-Stone intra-warp scan; build L = P^lane on the fly
    float LA[OCH] = {1.f, 1.f}, LB[OCH] = {1.f, 1.f}, LC[OCH] = {0.f, 0.f};

    #pragma unroll
    for (int d = 1; d <= 16; d <<= 1) {
        #pragma unroll
        for (int o = 0; o < OCH; o++) {
            if (lane & d) {
                const float nA = LA[o] * PA[o];
                const float nB = LB[o] * PB[o];
                const float nC = fmaf(LC[o], PA[o], LB[o] * PC[o]);
                LA[o] = nA; LB[o] = nB; LC[o] = nC;
            }
        }
        #pragma unroll
        for (int o = 0; o < OCH; o++) {
            const float ws = __shfl_up_sync(0xffffffffu, vs[o], d);
            const float wq = __shfl_up_sync(0xffffffffu, vm[o], d);
            if (lane >= d) {
                vm[o] = fmaf(PC[o], ws, fmaf(PB[o], wq, vm[o]));
                vs[o] = fmaf(PA[o], ws, vs[o]);
            }
        }
        #pragma unroll
        for (int o = 0; o < OCH; o++) {
            PC[o] = PC[o] * (PA[o] + PB[o]);
            PA[o] = PA[o] * PA[o];
            PB[o] = PB[o] * PB[o];
        }
    }
    // P now holds P^32 (warp-span matrix)

    if (lane == 31) {
        #pragma unroll
        for (int o = 0; o < OCH; o++) {
            Ts[o][w][0] = vs[o];
            Ts[o][w][1] = vm[o];
        }
    }
    __syncthreads();

    if (j < OCH) {
        const int o = j;
        float Ss = 0.f, Sm = 0.f;
        #pragma unroll
        for (int k = 0; k < 8; k++) {
            Es[o][k][0] = Ss;
            Es[o][k][1] = Sm;
            const float ts = Ts[o][k][0];
            const float tm = Ts[o][k][1];
            const float ns = fmaf(PA[o], Ss, ts);
            const float nm = fmaf(PC[o], Ss, fmaf(PB[o], Sm, tm));
            Ss = ns; Sm = nm;
        }
    }
    __syncthreads();

    // phase C: chunk prefix = P^lane * E_w + intra-warp exclusive; replay & store
    if (live) {
        float2* ob = reinterpret_cast<float2*>(out) + (size_t)b * TSTEPS + t0;
        float pre_s[OCH], pre_m[OCH];
        #pragma unroll
        for (int o = 0; o < OCH; o++) {
            float Xs = __shfl_up_sync(0xffffffffu, vs[o], 1);
            float Xm = __shfl_up_sync(0xffffffffu, vm[o], 1);
            if (lane == 0) { Xs = 0.f; Xm = 0.f; }
            const float es = Es[o][w][0];
            const float em = Es[o][w][1];
            pre_s[o] = fmaf(LA[o], es, Xs);
            pre_m[o] = fmaf(LC[o], es, fmaf(LB[o], em, Xm));
        }
        float s0 = pre_s[0], q0 = pre_m[0];
        float s1 = pre_s[1], q1 = pre_m[1];
        #pragma unroll
        for (int k = 0; k < CHUNK; k++) {
            s0 = fmaf(a[0], s0, c[0][k]); q0 = fmaf(m[0], q0, s0);
            s1 = fmaf(a[1], s1, c[1][k]); q1 = fmaf(m[1], q1, s1);
            ob[k] = make_float2(q0, q1);
        }
    }
}

extern "C" void kernel_launch(void* const* d_in, const int* in_sizes, int n_in,
                              void* d_out, int out_size)
{
    const float* inp   = (const float*)d_in[0]; // [256,182,2000]
    const float* W     = (const float*)d_in[1]; // [2,182]
    const float* bias  = (const float*)d_in[2]; // [2]
    const float* alpha = (const float*)d_in[3]; // [2]
    const float* beta  = (const float*)d_in[4]; // [2]
    float* out = (float*)d_out;                 // [256,2000,2]

    snn_fused_kernel<<<GRID, 256>>>(inp, W, bias, alpha, beta, out);
}